// round 1
// baseline (speedup 1.0000x reference)
#include <cuda_runtime.h>
#include <cstdint>

// Problem constants (fixed by the reference).
#define NP    16384
#define FIN   64
#define MC    4096
#define KN    64
#define FH    64
#define FO    128
#define FD    67          // FIN + 3
#define FPAD  68          // padded feature stride (bank-conflict-free, 16B aligned)
#define R2F   0.04f       // fp32(0.2*0.2)

// Scratch (static __device__ — no allocations allowed).
__device__ int   g_idx[MC];
__device__ float g_pos_s[MC * 3];
__device__ int   g_nbr[MC * KN];
__device__ int   g_cnt[MC];

// ---------------------------------------------------------------------------
// 1) Farthest point sampling — single persistent CTA (sequential dependency).
//    x,y coords + min_d2 live in registers (32 pts/thread), z in smem.
//    Argmax with lowest-index tie rule via monotonic packed u64 atomicMax.
// ---------------------------------------------------------------------------
#define FPS_T 512
#define FPS_P (NP / FPS_T)          // 32
#define FPS_SMEM (NP * 4 + 16 + 16)

__global__ __launch_bounds__(FPS_T) void fps_kernel(const float* __restrict__ pos)
{
    extern __shared__ unsigned char smem_raw[];
    float* s_pz = (float*)smem_raw;                                   // [NP]
    float* s_q  = (float*)(smem_raw + NP * 4);                        // [3]
    unsigned long long* s_key = (unsigned long long*)(smem_raw + NP * 4 + 16); // [2]

    int t = threadIdx.x;
    float px[FPS_P], py[FPS_P], md[FPS_P];
#pragma unroll
    for (int i = 0; i < FPS_P; i++) {
        int j = i * FPS_T + t;
        px[i] = pos[3 * j + 0];
        py[i] = pos[3 * j + 1];
        s_pz[j] = pos[3 * j + 2];
        md[i] = __int_as_float(0x7f800000);   // +inf
    }
    if (t == 0) {
        g_idx[0] = 0;
        s_q[0] = pos[0]; s_q[1] = pos[1]; s_q[2] = pos[2];
        s_key[0] = 0ull; s_key[1] = 0ull;
    }
    __syncthreads();

    for (int it = 1; it < MC; it++) {
        float qx = s_q[0], qy = s_q[1], qz = s_q[2];
        float bestv = -1.0f; int besti = 0;
#pragma unroll
        for (int i = 0; i < FPS_P; i++) {
            // Bit-exact replication of XLA's fused d2 = fma(dz,dz,fma(dy,dy,dx*dx))
            float dx = __fadd_rn(px[i], -qx);
            float dy = __fadd_rn(py[i], -qy);
            float dz = __fadd_rn(s_pz[i * FPS_T + t], -qz);
            float d2 = __fmaf_rn(dz, dz, __fmaf_rn(dy, dy, __fmul_rn(dx, dx)));
            float m = fminf(md[i], d2);
            md[i] = m;
            if (m > bestv) { bestv = m; besti = i; }   // strict > : first max, i.e. lowest j
        }
        unsigned bj = (unsigned)(besti * FPS_T + t);
        // d2 >= 0 always -> float bits are order-preserving; ~j makes ties pick lowest index.
        unsigned long long key = ((unsigned long long)__float_as_uint(bestv) << 32)
                               | (unsigned long long)(0xFFFFFFFFu - bj);
#pragma unroll
        for (int o = 16; o > 0; o >>= 1) {
            unsigned long long other = __shfl_down_sync(0xFFFFFFFFu, key, o);
            if (other > key) key = other;
        }
        int slot = it & 1;
        if ((t & 31) == 0) atomicMax(&s_key[slot], key);
        __syncthreads();
        unsigned long long k = s_key[slot];
        int nxt = (int)(0xFFFFFFFFu - (unsigned)(k & 0xFFFFFFFFull));
        if (t == 0) { g_idx[it] = nxt; s_key[slot ^ 1] = 0ull; }
        if ((nxt & (FPS_T - 1)) == t) {               // owner publishes next query point
            int i = nxt >> 9;                          // nxt / FPS_T (FPS_T == 512)
            s_q[0] = px[i]; s_q[1] = py[i]; s_q[2] = s_pz[nxt];
        }
        __syncthreads();
    }
}

// ---------------------------------------------------------------------------
// 2) Gather sampled positions; also emit pos_s / batch_s tail of the output
//    if out_size indicates the harness flattened the full tuple.
// ---------------------------------------------------------------------------
__global__ void gather_kernel(const float* __restrict__ pos, float* __restrict__ out, int out_size)
{
    int c = blockIdx.x * blockDim.x + threadIdx.x;
    if (c >= MC) return;
    int j = g_idx[c];
    float x = pos[3 * j + 0], y = pos[3 * j + 1], z = pos[3 * j + 2];
    g_pos_s[3 * c + 0] = x; g_pos_s[3 * c + 1] = y; g_pos_s[3 * c + 2] = z;
    int base = MC * FO;
    if (out_size >= base + 3 * MC) {
        out[base + 3 * c + 0] = x; out[base + 3 * c + 1] = y; out[base + 3 * c + 2] = z;
    }
    if (out_size >= base + 4 * MC) out[base + 3 * MC + c] = 0.0f;  // batch_s == 0 (same bits as int 0)
}

// ---------------------------------------------------------------------------
// 3) Radius neighbors: 16 centers/block stream all points once.
//    Order in the list is irrelevant (set semantics downstream); if count>K,
//    rank-select the K smallest by (d2, idx) to match top_k's stable ties.
// ---------------------------------------------------------------------------
#define RB_C   16
#define RB_T   256
#define RB_CAP 192

__global__ __launch_bounds__(RB_T) void radius_kernel(const float* __restrict__ pos)
{
    __shared__ float scx[RB_C], scy[RB_C], scz[RB_C];
    __shared__ int   scnt[RB_C];
    __shared__ int   sidx[RB_C][RB_CAP];
    __shared__ float sd2[RB_C][RB_CAP];

    int t = threadIdx.x;
    int c0 = blockIdx.x * RB_C;
    if (t < RB_C) {
        scx[t] = g_pos_s[3 * (c0 + t) + 0];
        scy[t] = g_pos_s[3 * (c0 + t) + 1];
        scz[t] = g_pos_s[3 * (c0 + t) + 2];
        scnt[t] = 0;
    }
    __syncthreads();

    for (int j = t; j < NP; j += RB_T) {
        float x = pos[3 * j + 0], y = pos[3 * j + 1], z = pos[3 * j + 2];
#pragma unroll
        for (int c = 0; c < RB_C; c++) {
            float dx = __fadd_rn(scx[c], -x);
            float dy = __fadd_rn(scy[c], -y);
            float dz = __fadd_rn(scz[c], -z);
            float d2 = __fmaf_rn(dz, dz, __fmaf_rn(dy, dy, __fmul_rn(dx, dx)));
            if (d2 <= R2F) {
                int n = atomicAdd(&scnt[c], 1);
                if (n < RB_CAP) { sidx[c][n] = j; sd2[c][n] = d2; }
            }
        }
    }
    __syncthreads();

    for (int c = 0; c < RB_C; c++) {
        int cnt = min(scnt[c], RB_CAP);
        int cg = c0 + c;
        if (cnt <= KN) {
            if (t < cnt) g_nbr[cg * KN + t] = sidx[c][t];
            if (t == 0)  g_cnt[cg] = cnt;
        } else {
            for (int i = t; i < cnt; i += RB_T) {
                float di = sd2[c][i]; int ii = sidx[c][i];
                int rank = 0;
                for (int jj = 0; jj < cnt; jj++) {
                    float dj = sd2[c][jj];
                    rank += (dj < di) || (dj == di && sidx[c][jj] < ii);
                }
                if (rank < KN) g_nbr[cg * KN + rank] = ii;
            }
            if (t == 0) g_cnt[cg] = KN;
        }
    }
}

// ---------------------------------------------------------------------------
// 4) Per-edge MLP (67->64->64->128, relu) + max-pool. Persistent grid,
//    weights resident in smem, register-tiled so the fp32 FMA pipe binds.
// ---------------------------------------------------------------------------
#define ML_T    256
#define ML_GRID 304

#define OFF_W1 0
#define OFF_W2 (OFF_W1 + FD * FH)
#define OFF_W3 (OFF_W2 + FH * FH)
#define OFF_B1 (OFF_W3 + FH * FO)
#define OFF_B2 (OFF_B1 + FH)
#define OFF_B3 (OFF_B2 + FH)
#define OFF_F  (OFF_B3 + FO)
#define OFF_H  (OFF_F + KN * FPAD)
#define OFF_O  (OFF_H + KN * FPAD)
#define ML_SMEM ((OFF_O + FO) * 4)

__global__ __launch_bounds__(ML_T, 2) void mlp_kernel(
    const float* __restrict__ x, const float* __restrict__ pos,
    const float* __restrict__ W1, const float* __restrict__ b1,
    const float* __restrict__ W2, const float* __restrict__ b2,
    const float* __restrict__ W3, const float* __restrict__ b3,
    float* __restrict__ out)
{
    extern __shared__ float sm[];
    float* sW1 = sm + OFF_W1;
    float* sW2 = sm + OFF_W2;
    float* sW3 = sm + OFF_W3;
    float* sb1 = sm + OFF_B1;
    float* sb2 = sm + OFF_B2;
    float* sb3 = sm + OFF_B3;
    float* sF  = sm + OFF_F;   // features, later reused as h2
    float* sH  = sm + OFF_H;   // h1
    int*   sO  = (int*)(sm + OFF_O);

    int t = threadIdx.x;
    for (int i = t; i < FD * FH; i += ML_T) sW1[i] = W1[i];
    for (int i = t; i < FH * FH; i += ML_T) sW2[i] = W2[i];
    for (int i = t; i < FH * FO; i += ML_T) sW3[i] = W3[i];
    if (t < FH) { sb1[t] = b1[t]; sb2[t] = b2[t]; }
    if (t < FO) sb3[t] = b3[t];

    int ei = t >> 4, ci = t & 15;

    for (int c = blockIdx.x; c < MC; c += gridDim.x) {
        __syncthreads();
        if (t < FO) sO[t] = 0;   // relu output max is always >= 0 (E >= 1)
        int E = g_cnt[c];
        float cx = g_pos_s[3 * c + 0], cy = g_pos_s[3 * c + 1], cz = g_pos_s[3 * c + 2];

        // Build feature rows: [E, 67] = [x[nbr] | pos[nbr]-pos_s]
        {
            int e = t >> 2, q = t & 3;
            if (e < E) {
                int nb = g_nbr[c * KN + e];
                const float4* xr = (const float4*)(x + (size_t)nb * FIN);
                float4* dst = (float4*)(sF + e * FPAD + q * 16);
                dst[0] = xr[q * 4 + 0]; dst[1] = xr[q * 4 + 1];
                dst[2] = xr[q * 4 + 2]; dst[3] = xr[q * 4 + 3];
                if (q == 0) {
                    sF[e * FPAD + 64] = pos[3 * nb + 0] - cx;
                    sF[e * FPAD + 65] = pos[3 * nb + 1] - cy;
                    sF[e * FPAD + 66] = pos[3 * nb + 2] - cz;
                    sF[e * FPAD + 67] = 0.0f;
                }
            }
        }
        __syncthreads();
        int ET = (E + 3) >> 2;   // active 4-edge tiles

        // Layer 1: [E,67] @ [67,64] -> sH
        if (ei < ET) {
            float acc[4][4];
#pragma unroll
            for (int j = 0; j < 4; j++)
#pragma unroll
                for (int a = 0; a < 4; a++) acc[j][a] = sb1[ci * 4 + a];
#pragma unroll 4
            for (int k = 0; k < FD; k++) {
                float4 w = *(const float4*)(sW1 + k * FH + ci * 4);
                float f[4];
#pragma unroll
                for (int j = 0; j < 4; j++) f[j] = sF[(4 * ei + j) * FPAD + k];
#pragma unroll
                for (int j = 0; j < 4; j++) {
                    acc[j][0] += f[j] * w.x; acc[j][1] += f[j] * w.y;
                    acc[j][2] += f[j] * w.z; acc[j][3] += f[j] * w.w;
                }
            }
#pragma unroll
            for (int j = 0; j < 4; j++)
#pragma unroll
                for (int a = 0; a < 4; a++)
                    sH[(4 * ei + j) * FPAD + ci * 4 + a] = fmaxf(acc[j][a], 0.0f);
        }
        __syncthreads();

        // Layer 2: [E,64] @ [64,64] -> sF (reuse)
        if (ei < ET) {
            float acc[4][4];
#pragma unroll
            for (int j = 0; j < 4; j++)
#pragma unroll
                for (int a = 0; a < 4; a++) acc[j][a] = sb2[ci * 4 + a];
#pragma unroll 4
            for (int k = 0; k < FH; k++) {
                float4 w = *(const float4*)(sW2 + k * FH + ci * 4);
                float f[4];
#pragma unroll
                for (int j = 0; j < 4; j++) f[j] = sH[(4 * ei + j) * FPAD + k];
#pragma unroll
                for (int j = 0; j < 4; j++) {
                    acc[j][0] += f[j] * w.x; acc[j][1] += f[j] * w.y;
                    acc[j][2] += f[j] * w.z; acc[j][3] += f[j] * w.w;
                }
            }
#pragma unroll
            for (int j = 0; j < 4; j++)
#pragma unroll
                for (int a = 0; a < 4; a++)
                    sF[(4 * ei + j) * FPAD + ci * 4 + a] = fmaxf(acc[j][a], 0.0f);
        }
        __syncthreads();

        // Layer 3: [E,64] @ [64,128] + relu + masked max over edges
        if (ei < ET) {
            float acc[4][8];
#pragma unroll
            for (int j = 0; j < 4; j++)
#pragma unroll
                for (int a = 0; a < 8; a++) acc[j][a] = sb3[ci * 8 + a];
#pragma unroll 4
            for (int k = 0; k < FH; k++) {
                float4 wa = *(const float4*)(sW3 + k * FO + ci * 8);
                float4 wb = *(const float4*)(sW3 + k * FO + ci * 8 + 4);
                float f[4];
#pragma unroll
                for (int j = 0; j < 4; j++) f[j] = sF[(4 * ei + j) * FPAD + k];
#pragma unroll
                for (int j = 0; j < 4; j++) {
                    acc[j][0] += f[j] * wa.x; acc[j][1] += f[j] * wa.y;
                    acc[j][2] += f[j] * wa.z; acc[j][3] += f[j] * wa.w;
                    acc[j][4] += f[j] * wb.x; acc[j][5] += f[j] * wb.y;
                    acc[j][6] += f[j] * wb.z; acc[j][7] += f[j] * wb.w;
                }
            }
#pragma unroll
            for (int a = 0; a < 8; a++) {
                float mv = -1.0f;
#pragma unroll
                for (int j = 0; j < 4; j++)
                    if (4 * ei + j < E) mv = fmaxf(mv, fmaxf(acc[j][a], 0.0f));
                if (mv >= 0.0f) atomicMax(&sO[ci * 8 + a], __float_as_int(mv));
            }
        }
        __syncthreads();
        if (t < FO) out[(size_t)c * FO + t] = __int_as_float(sO[t]);
    }
}

// ---------------------------------------------------------------------------
extern "C" void kernel_launch(void* const* d_in, const int* in_sizes, int n_in,
                              void* d_out, int out_size)
{
    const float* x   = (const float*)d_in[0];
    const float* pos = (const float*)d_in[1];
    // d_in[2] = batch (all zeros, unused)
    const float* W1 = (const float*)d_in[3];
    const float* b1 = (const float*)d_in[4];
    const float* W2 = (const float*)d_in[5];
    const float* b2 = (const float*)d_in[6];
    const float* W3 = (const float*)d_in[7];
    const float* b3 = (const float*)d_in[8];
    float* out = (float*)d_out;

    cudaFuncSetAttribute(fps_kernel, cudaFuncAttributeMaxDynamicSharedMemorySize, FPS_SMEM);
    cudaFuncSetAttribute(mlp_kernel, cudaFuncAttributeMaxDynamicSharedMemorySize, ML_SMEM);

    fps_kernel<<<1, FPS_T, FPS_SMEM>>>(pos);
    gather_kernel<<<(MC + 255) / 256, 256>>>(pos, out, out_size);
    radius_kernel<<<MC / RB_C, RB_T>>>(pos);
    mlp_kernel<<<ML_GRID, ML_T, ML_SMEM>>>(x, pos, W1, b1, W2, b2, W3, b3, out);
}